// round 14
// baseline (speedup 1.0000x reference)
#include <cuda_runtime.h>

#define TT 512
#define BB 16384
#define HH 32
#define RL 4              // batch lanes per thread
#define BLK 256
#define LPC 128           // lanes per CTA; 8 threads per lane (4 quarters x 2 k-halves)
#define WST 36            // weight row stride (floats)
#define WHALF (16*WST+4)  // k-half-1 weight rows offset (+4 shift kills q x h collisions)
#define RST 18            // act row stride (u64) within a half-region
#define R1B (128*RST+8)   // region-1 base (u64); +8 pad => +16 bank shift for h

typedef unsigned long long u64;

// ---- packed f32x2 helpers (PTX-only; ptxas never auto-fuses) ----
__device__ __forceinline__ u64 fma2(u64 a, u64 b, u64 c) {
    u64 d; asm("fma.rn.f32x2 %0,%1,%2,%3;" : "=l"(d) : "l"(a), "l"(b), "l"(c)); return d;
}
__device__ __forceinline__ u64 mul2(u64 a, u64 b) {
    u64 d; asm("mul.rn.f32x2 %0,%1,%2;" : "=l"(d) : "l"(a), "l"(b)); return d;
}
__device__ __forceinline__ u64 add2(u64 a, u64 b) {
    u64 d; asm("add.rn.f32x2 %0,%1,%2;" : "=l"(d) : "l"(a), "l"(b)); return d;
}
__device__ __forceinline__ u64 pack2(float lo, float hi) {
    u64 r; asm("mov.b64 %0,{%1,%2};" : "=l"(r) : "f"(lo), "f"(hi)); return r;
}
__device__ __forceinline__ u64 dup2(float x) { return pack2(x, x); }
__device__ __forceinline__ void unpack2(u64 v, float& lo, float& hi) {
    asm("mov.b64 {%0,%1},%2;" : "=f"(lo), "=f"(hi) : "l"(v));
}
__device__ __forceinline__ u64 shfl_xor64(u64 v, int m) {
    return (u64)__shfl_xor_sync(0xffffffffu, (long long)v, m);
}

// stable softplus + sigmoid sharing one exp
__device__ __forceinline__ void sp_sig(float z, float& sp, float& sg) {
    float u = __expf(-fabsf(z));
    float d = 1.0f + u;
    float r = __fdividef(1.0f, d);
    sp = fmaxf(z, 0.0f) + __logf(d);
    sg = (z >= 0.0f) ? r : 1.0f - r;
}
__device__ __forceinline__ float sigf(float z) {
    float u = __expf(-fabsf(z));
    float r = __fdividef(1.0f, 1.0f + u);
    return (z >= 0.0f) ? r : 1.0f - r;
}

__global__ void __launch_bounds__(BLK, 1) rnncell_dupact_kernel(
    const float* __restrict__ eps, const float* __restrict__ hs,
    const float* __restrict__ W1,  const float* __restrict__ b1,
    const float* __restrict__ W2,  const float* __restrict__ b2,
    const float* __restrict__ W3,  float* __restrict__ out)
{
    __shared__ __align__(16) float sW2 [2 * WHALF + 64];   // W2[k][j]
    __shared__ __align__(16) float sW2T[2 * WHALF + 64];   // W2T[j][k]
    __shared__ __align__(16) u64   sAct[R1B + 128 * RST];  // dup-packed acts, 2 regions

    const int tid = threadIdx.x;
    for (int i = tid; i < HH * HH; i += BLK) {
        const int k = i >> 5, j = i & 31;
        const float w = W2[i];
        sW2 [k * WST + ((k >> 4) << 2) + j] = w;   // row k, col j
        sW2T[j * WST + ((j >> 4) << 2) + k] = w;   // row j, col k
    }
    __syncthreads();

    const int q   = tid & 3;          // output-chunk quarter (8 units)
    const int h   = (tid >> 2) & 1;   // k-half
    const int grp = tid >> 3;         // group 0..31, serves 4 lanes
    const int co  = q * 8;            // 8-col/row block base
    const int uo  = co + h * 4;       // my 4 units (L1 / V2 / epilogue)

    const float* sW2h  = sW2  + h * WHALF;   // my 16 weight rows (MV1)
    const float* sW2Th = sW2T + h * WHALF;   // my 16 weight rows (MV2)

    const int gbase = blockIdx.x * LPC + grp * RL;   // 4 consecutive gids

    // act addressing: lane row = grp + 32*r; unit k<16 in region0 at row*RST+k,
    // k>=16 in region1 at R1B+row*RST+(k-16). Consumer (fixed kb,m) banks:
    // {4*grp + 16*h} -> 8 distinct, 4-way q-broadcast, conflict-free.
    int mybase[RL];   // where I READ my k-half for lane r
    int sbase [RL];   // where I WRITE my 4 units for lane r
    #pragma unroll
    for (int r = 0; r < RL; ++r) {
        const int rowb = (grp + 32 * r) * RST;
        mybase[r] = h ? (R1B + rowb) : rowb;
        sbase [r] = (uo < 16) ? (rowb + uo) : (R1B + rowb + (uo - 16));
    }

    // per-thread weights: my 4 units scalar + packed
    float w1a4[4], w1b4[4], b14[4], w34[4];
    #pragma unroll
    for (int j = 0; j < 4; ++j) {
        w1a4[j] = W1[uo + j];
        w1b4[j] = W1[HH + uo + j];
        b14 [j] = b1[uo + j];
        w34 [j] = W3[uo + j];
    }
    u64 w1apk[2], w1bpk[2];
    #pragma unroll
    for (int j = 0; j < 2; ++j) {
        w1apk[j] = pack2(w1a4[2*j], w1a4[2*j + 1]);
        w1bpk[j] = pack2(w1b4[2*j], w1b4[2*j + 1]);
    }
    // b2 for my 8 cols; only the h==0 partial carries the bias
    u64 b2pk[4];
    #pragma unroll
    for (int j = 0; j < 4; ++j)
        b2pk[j] = h ? 0ull : pack2(b2[co + 2*j], b2[co + 2*j + 1]);

    float gam[RL], ec[RL], hc[RL];
    {
        float4 e4 = *(const float4*)(eps + gbase);
        float4 h4 = *(const float4*)(hs  + gbase);
        ec[0]=e4.x; ec[1]=e4.y; ec[2]=e4.z; ec[3]=e4.w;
        hc[0]=h4.x; hc[1]=h4.y; hc[2]=h4.z; hc[3]=h4.w;
        #pragma unroll
        for (int r = 0; r < RL; ++r) gam[r] = 0.0f;
    }

    for (int t = 0; t < TT; ++t) {
        const int tn = (t + 1 < TT) ? t + 1 : t;
        float4 en4 = *(const float4*)(eps + (size_t)tn * BB + gbase);
        float4 hn4 = *(const float4*)(hs  + (size_t)tn * BB + gbase);

        // ---- layer 1: my 4 units x 4 lanes -> softplus dup-staged, sigmoid kept
        u64 s1p[RL][2];
        #pragma unroll
        for (int r = 0; r < RL; ++r) {
            float a1v[4], sgv[4];
            #pragma unroll
            for (int j = 0; j < 4; ++j) {
                float z = fmaf(ec[r], w1a4[j], fmaf(gam[r], w1b4[j], b14[j]));
                sp_sig(z, a1v[j], sgv[j]);
            }
            s1p[r][0] = pack2(sgv[0], sgv[1]);
            s1p[r][1] = pack2(sgv[2], sgv[3]);
            *(ulonglong2*)(sAct + sbase[r])     = make_ulonglong2(dup2(a1v[0]), dup2(a1v[1]));
            *(ulonglong2*)(sAct + sbase[r] + 2) = make_ulonglong2(dup2(a1v[2]), dup2(a1v[3]));
        }
        __syncwarp();

        // ---- MV1 partial: cols [co,co+8), my 16 k's; acts pre-duplicated ----
        u64 acc[RL][4];
        #pragma unroll
        for (int r = 0; r < RL; ++r)
            #pragma unroll
            for (int j = 0; j < 4; ++j) acc[r][j] = b2pk[j];

        #pragma unroll
        for (int kb = 0; kb < 2; ++kb) {
            u64 av[RL][8];
            #pragma unroll
            for (int r = 0; r < RL; ++r) {
                ulonglong2 t0 = *(const ulonglong2*)(sAct + mybase[r] + kb*8 + 0);
                ulonglong2 t1 = *(const ulonglong2*)(sAct + mybase[r] + kb*8 + 2);
                ulonglong2 t2 = *(const ulonglong2*)(sAct + mybase[r] + kb*8 + 4);
                ulonglong2 t3 = *(const ulonglong2*)(sAct + mybase[r] + kb*8 + 6);
                av[r][0]=t0.x; av[r][1]=t0.y; av[r][2]=t1.x; av[r][3]=t1.y;
                av[r][4]=t2.x; av[r][5]=t2.y; av[r][6]=t3.x; av[r][7]=t3.y;
            }
            #pragma unroll
            for (int kk = 0; kk < 8; ++kk) {
                const float* wr = sW2h + (kb * 8 + kk) * WST + co;
                ulonglong2 wlo = *(const ulonglong2*)wr;
                ulonglong2 whi = *(const ulonglong2*)(wr + 4);
                #pragma unroll
                for (int r = 0; r < RL; ++r) {
                    acc[r][0] = fma2(av[r][kk], wlo.x, acc[r][0]);
                    acc[r][1] = fma2(av[r][kk], wlo.y, acc[r][1]);
                    acc[r][2] = fma2(av[r][kk], whi.x, acc[r][2]);
                    acc[r][3] = fma2(av[r][kk], whi.y, acc[r][3]);
                }
            }
        }
        // combine with k-half partner (xor 4): full sums for MY col-pairs
        u64 accf[RL][2];
        #pragma unroll
        for (int r = 0; r < RL; ++r) {
            u64 mine0 = h ? acc[r][2] : acc[r][0];
            u64 mine1 = h ? acc[r][3] : acc[r][1];
            u64 send0 = h ? acc[r][0] : acc[r][2];
            u64 send1 = h ? acc[r][1] : acc[r][3];
            accf[r][0] = add2(mine0, shfl_xor64(send0, 4));
            accf[r][1] = add2(mine1, shfl_xor64(send1, 4));
        }
        __syncwarp();   // all MV1 act reads done before V2 overwrites

        // ---- V2: my 4 cols, sigmoid * W3, dup-staged ----
        #pragma unroll
        for (int r = 0; r < RL; ++r) {
            float za, zb, zc, zd;
            unpack2(accf[r][0], za, zb);
            unpack2(accf[r][1], zc, zd);
            *(ulonglong2*)(sAct + sbase[r]) =
                make_ulonglong2(dup2(sigf(za) * w34[0]), dup2(sigf(zb) * w34[1]));
            *(ulonglong2*)(sAct + sbase[r] + 2) =
                make_ulonglong2(dup2(sigf(zc) * w34[2]), dup2(sigf(zd) * w34[3]));
        }
        __syncwarp();

        // ---- MV2 partial: rows [co,co+8), my 16 j's ----
        u64 tacc[RL][4];
        #pragma unroll
        for (int r = 0; r < RL; ++r)
            #pragma unroll
            for (int j = 0; j < 4; ++j) tacc[r][j] = 0ull;

        #pragma unroll
        for (int kb = 0; kb < 2; ++kb) {
            u64 vv[RL][8];
            #pragma unroll
            for (int r = 0; r < RL; ++r) {
                ulonglong2 t0 = *(const ulonglong2*)(sAct + mybase[r] + kb*8 + 0);
                ulonglong2 t1 = *(const ulonglong2*)(sAct + mybase[r] + kb*8 + 2);
                ulonglong2 t2 = *(const ulonglong2*)(sAct + mybase[r] + kb*8 + 4);
                ulonglong2 t3 = *(const ulonglong2*)(sAct + mybase[r] + kb*8 + 6);
                vv[r][0]=t0.x; vv[r][1]=t0.y; vv[r][2]=t1.x; vv[r][3]=t1.y;
                vv[r][4]=t2.x; vv[r][5]=t2.y; vv[r][6]=t3.x; vv[r][7]=t3.y;
            }
            #pragma unroll
            for (int kk = 0; kk < 8; ++kk) {
                const float* wr = sW2Th + (kb * 8 + kk) * WST + co;
                ulonglong2 wlo = *(const ulonglong2*)wr;
                ulonglong2 whi = *(const ulonglong2*)(wr + 4);
                #pragma unroll
                for (int r = 0; r < RL; ++r) {
                    tacc[r][0] = fma2(vv[r][kk], wlo.x, tacc[r][0]);
                    tacc[r][1] = fma2(vv[r][kk], wlo.y, tacc[r][1]);
                    tacc[r][2] = fma2(vv[r][kk], whi.x, tacc[r][2]);
                    tacc[r][3] = fma2(vv[r][kk], whi.y, tacc[r][3]);
                }
            }
        }
        // combine: full t for MY row-pairs
        u64 tf[RL][2];
        #pragma unroll
        for (int r = 0; r < RL; ++r) {
            u64 mine0 = h ? tacc[r][2] : tacc[r][0];
            u64 mine1 = h ? tacc[r][3] : tacc[r][1];
            u64 send0 = h ? tacc[r][0] : tacc[r][2];
            u64 send1 = h ? tacc[r][1] : tacc[r][3];
            tf[r][0] = add2(mine0, shfl_xor64(send0, 4));
            tf[r][1] = add2(mine1, shfl_xor64(send1, 4));
        }
        __syncwarp();   // MV2 act reads done before next iteration's L1 stores

        // ---- epilogue: v1 = sig1 .* t over my 4 rows; dots; 8-thread butterfly ----
        float g0[RL], g1[RL];
        #pragma unroll
        for (int r = 0; r < RL; ++r) {
            u64 v10 = mul2(s1p[r][0], tf[r][0]);
            u64 v11 = mul2(s1p[r][1], tf[r][1]);
            u64 g0p = fma2(v11, w1apk[1], mul2(v10, w1apk[0]));
            u64 g1p = fma2(v11, w1bpk[1], mul2(v10, w1bpk[0]));
            float a, b;
            unpack2(g0p, a, b); g0[r] = a + b;
            unpack2(g1p, a, b); g1[r] = a + b;
        }
        #pragma unroll
        for (int r = 0; r < RL; ++r) {
            u64 G = pack2(g0[r], g1[r]);            // reduce both together
            G = add2(G, shfl_xor64(G, 1));
            G = add2(G, shfl_xor64(G, 2));
            G = add2(G, shfl_xor64(G, 4));
            unpack2(G, g0[r], g1[r]);
        }

        if ((tid & 7) == 0)
            *(float4*)(out + (size_t)t * BB + gbase) =
                make_float4(g0[0], g0[1], g0[2], g0[3]);

        gam[0] = fmaf(hc[0], -g1[0], gam[0]);
        gam[1] = fmaf(hc[1], -g1[1], gam[1]);
        gam[2] = fmaf(hc[2], -g1[2], gam[2]);
        gam[3] = fmaf(hc[3], -g1[3], gam[3]);

        ec[0]=en4.x; ec[1]=en4.y; ec[2]=en4.z; ec[3]=en4.w;
        hc[0]=hn4.x; hc[1]=hn4.y; hc[2]=hn4.z; hc[3]=hn4.w;
    }
}

extern "C" void kernel_launch(void* const* d_in, const int* in_sizes, int n_in,
                              void* d_out, int out_size) {
    const float* eps = (const float*)d_in[0];
    const float* hs  = (const float*)d_in[1];
    const float* W1  = (const float*)d_in[2];
    const float* b1  = (const float*)d_in[3];
    const float* W2  = (const float*)d_in[4];
    const float* b2  = (const float*)d_in[5];
    const float* W3  = (const float*)d_in[6];
    float* out = (float*)d_out;

    // 128 CTAs x 256 threads: 2 warps/SMSP on 128 SMs, split-K over 2 threads,
    // activations staged pre-duplicated (no dup MOVs in matvec loops)
    rnncell_dupact_kernel<<<BB / LPC, BLK>>>(eps, hs, W1, b1, W2, b2, W3, out);
}

// round 16
// speedup vs baseline: 1.0084x; 1.0084x over previous
#include <cuda_runtime.h>

#define TT 512
#define BB 16384
#define HH 32
#define RL 4              // batch lanes per thread
#define BLK 512
#define LPC 128           // lanes per CTA; 16 threads per lane (4 col-q x 4 k-q)
#define AST 36            // act row stride (floats)
#define WST 36            // weight row stride (floats)

typedef unsigned long long u64;

// ---- packed f32x2 helpers (PTX-only; ptxas never auto-fuses) ----
__device__ __forceinline__ u64 fma2(u64 a, u64 b, u64 c) {
    u64 d; asm("fma.rn.f32x2 %0,%1,%2,%3;" : "=l"(d) : "l"(a), "l"(b), "l"(c)); return d;
}
__device__ __forceinline__ u64 mul2(u64 a, u64 b) {
    u64 d; asm("mul.rn.f32x2 %0,%1,%2;" : "=l"(d) : "l"(a), "l"(b)); return d;
}
__device__ __forceinline__ u64 add2(u64 a, u64 b) {
    u64 d; asm("add.rn.f32x2 %0,%1,%2;" : "=l"(d) : "l"(a), "l"(b)); return d;
}
__device__ __forceinline__ u64 pack2(float lo, float hi) {
    u64 r; asm("mov.b64 %0,{%1,%2};" : "=l"(r) : "f"(lo), "f"(hi)); return r;
}
__device__ __forceinline__ u64 dup2(float x) { return pack2(x, x); }
__device__ __forceinline__ void unpack2(u64 v, float& lo, float& hi) {
    asm("mov.b64 {%0,%1},%2;" : "=f"(lo), "=f"(hi) : "l"(v));
}
__device__ __forceinline__ u64 shfl_xor64(u64 v, int m) {
    return (u64)__shfl_xor_sync(0xffffffffu, (long long)v, m);
}

// stable softplus + sigmoid sharing one exp
__device__ __forceinline__ void sp_sig(float z, float& sp, float& sg) {
    float u = __expf(-fabsf(z));
    float d = 1.0f + u;
    float r = __fdividef(1.0f, d);
    sp = fmaxf(z, 0.0f) + __logf(d);
    sg = (z >= 0.0f) ? r : 1.0f - r;
}
__device__ __forceinline__ float sigf(float z) {
    float u = __expf(-fabsf(z));
    float r = __fdividef(1.0f, 1.0f + u);
    return (z >= 0.0f) ? r : 1.0f - r;
}

__global__ void __launch_bounds__(BLK, 1) rnncell_q4_kernel(
    const float* __restrict__ eps, const float* __restrict__ hs,
    const float* __restrict__ W1,  const float* __restrict__ b1,
    const float* __restrict__ W2,  const float* __restrict__ b2,
    const float* __restrict__ W3,  float* __restrict__ out)
{
    // weight rows at k*36 + 4*(k>>3): per-k-quarter +4-float shift so the
    // 16 distinct (q,kq) addresses of each load spread across bank positions
    __shared__ __align__(16) float sW2 [31 * WST + 12 + 40];   // W2[k][j]
    __shared__ __align__(16) float sW2T[31 * WST + 12 + 40];   // W2T[j][k]
    __shared__ __align__(16) float sAct[LPC * AST];            // scalar act rows

    const int tid = threadIdx.x;
    for (int i = tid; i < HH * HH; i += BLK) {
        const int k = i >> 5, j = i & 31;
        const float w = W2[i];
        sW2 [k * WST + ((k >> 3) << 2) + j] = w;   // row k, col j
        sW2T[j * WST + ((j >> 3) << 2) + k] = w;   // row j, col k
    }
    __syncthreads();

    const int q   = tid & 3;          // col quarter (8 cols)
    const int kq  = (tid >> 2) & 3;   // k quarter (8 k's)
    const int grp = tid >> 4;         // group 0..31, serves 4 lanes
    const int co  = q * 8;
    const int uo  = co + kq * 2;      // my 2 units (L1 / V2 / epilogue)
    const int b0  = kq & 1;           // combine stage-1 keep selector
    const int b1s = kq & 2;           // combine stage-2 keep selector

    const float* pW1 = sW2  + kq * 8 * WST + kq * 4 + co;   // my 8 MV1 rows
    const float* pW2 = sW2T + kq * 8 * WST + kq * 4 + co;   // my 8 MV2 rows

    const int gbase = blockIdx.x * LPC + grp * RL;   // 4 consecutive gids

    float* arow[RL];
    #pragma unroll
    for (int r = 0; r < RL; ++r) arow[r] = sAct + (grp + 32 * r) * AST;

    // per-thread weights: my 2 units
    const float w1a0 = W1[uo],          w1a1 = W1[uo + 1];
    const float w1b0 = W1[HH + uo],     w1b1 = W1[HH + uo + 1];
    const float b10  = b1[uo],          b11  = b1[uo + 1];
    const float w30  = W3[uo],          w31  = W3[uo + 1];
    const u64 w1apk = pack2(w1a0, w1a1);
    const u64 w1bpk = pack2(w1b0, w1b1);

    // bias carried only by the kq==0 partial
    u64 b2pk[4];
    #pragma unroll
    for (int j = 0; j < 4; ++j)
        b2pk[j] = (kq == 0) ? pack2(b2[co + 2*j], b2[co + 2*j + 1]) : 0ull;

    float gam[RL], ec[RL], hc[RL];
    {
        float4 e4 = *(const float4*)(eps + gbase);
        float4 h4 = *(const float4*)(hs  + gbase);
        ec[0]=e4.x; ec[1]=e4.y; ec[2]=e4.z; ec[3]=e4.w;
        hc[0]=h4.x; hc[1]=h4.y; hc[2]=h4.z; hc[3]=h4.w;
        #pragma unroll
        for (int r = 0; r < RL; ++r) gam[r] = 0.0f;
    }

    for (int t = 0; t < TT; ++t) {
        const int tn = (t + 1 < TT) ? t + 1 : t;
        float4 en4 = *(const float4*)(eps + (size_t)tn * BB + gbase);
        float4 hn4 = *(const float4*)(hs  + (size_t)tn * BB + gbase);

        // ---- layer 1: my 2 units x 4 lanes ----
        u64 s1p[RL];
        #pragma unroll
        for (int r = 0; r < RL; ++r) {
            float z0 = fmaf(ec[r], w1a0, fmaf(gam[r], w1b0, b10));
            float z1 = fmaf(ec[r], w1a1, fmaf(gam[r], w1b1, b11));
            float sp0, sg0, sp1, sg1;
            sp_sig(z0, sp0, sg0);
            sp_sig(z1, sp1, sg1);
            s1p[r] = pack2(sg0, sg1);
            *(float2*)(arow[r] + uo) = make_float2(sp0, sp1);
        }
        __syncwarp();

        // ---- MV1 partial: cols [co,co+8), my 8 k's ----
        u64 acc[RL][4];
        #pragma unroll
        for (int r = 0; r < RL; ++r)
            #pragma unroll
            for (int j = 0; j < 4; ++j) acc[r][j] = b2pk[j];
        {
            float av[RL][8];
            #pragma unroll
            for (int r = 0; r < RL; ++r) {
                float4 lo = *(const float4*)(arow[r] + kq * 8);
                float4 hi = *(const float4*)(arow[r] + kq * 8 + 4);
                av[r][0]=lo.x; av[r][1]=lo.y; av[r][2]=lo.z; av[r][3]=lo.w;
                av[r][4]=hi.x; av[r][5]=hi.y; av[r][6]=hi.z; av[r][7]=hi.w;
            }
            #pragma unroll
            for (int kk = 0; kk < 8; ++kk) {
                const float* wr = pW1 + kk * WST;
                ulonglong2 wlo = *(const ulonglong2*)wr;
                ulonglong2 whi = *(const ulonglong2*)(wr + 4);
                #pragma unroll
                for (int r = 0; r < RL; ++r) {
                    u64 ak = dup2(av[r][kk]);
                    acc[r][0] = fma2(ak, wlo.x, acc[r][0]);
                    acc[r][1] = fma2(ak, wlo.y, acc[r][1]);
                    acc[r][2] = fma2(ak, whi.x, acc[r][2]);
                    acc[r][3] = fma2(ak, whi.y, acc[r][3]);
                }
            }
        }
        // combine over k-quarters: stage1 xor4 (kq bit0), stage2 xor8 (kq bit1)
        u64 accf[RL];
        #pragma unroll
        for (int r = 0; r < RL; ++r) {
            u64 keep0 = b0 ? acc[r][1] : acc[r][0];
            u64 send0 = b0 ? acc[r][0] : acc[r][1];
            u64 keep1 = b0 ? acc[r][3] : acc[r][2];
            u64 send1 = b0 ? acc[r][2] : acc[r][3];
            u64 a0 = add2(keep0, shfl_xor64(send0, 4));
            u64 a1 = add2(keep1, shfl_xor64(send1, 4));
            u64 mine  = b1s ? a1 : a0;
            u64 sendv = b1s ? a0 : a1;
            accf[r] = add2(mine, shfl_xor64(sendv, 8));
        }
        __syncwarp();   // all MV1 act reads done before V2 overwrites

        // ---- V2: my 2 cols, sigmoid * W3 ----
        #pragma unroll
        for (int r = 0; r < RL; ++r) {
            float z0, z1;
            unpack2(accf[r], z0, z1);
            *(float2*)(arow[r] + uo) = make_float2(sigf(z0) * w30, sigf(z1) * w31);
        }
        __syncwarp();

        // ---- MV2 partial: rows [co,co+8), my 8 j's ----
        u64 tacc[RL][4];
        #pragma unroll
        for (int r = 0; r < RL; ++r)
            #pragma unroll
            for (int j = 0; j < 4; ++j) tacc[r][j] = 0ull;
        {
            float vv[RL][8];
            #pragma unroll
            for (int r = 0; r < RL; ++r) {
                float4 lo = *(const float4*)(arow[r] + kq * 8);
                float4 hi = *(const float4*)(arow[r] + kq * 8 + 4);
                vv[r][0]=lo.x; vv[r][1]=lo.y; vv[r][2]=lo.z; vv[r][3]=lo.w;
                vv[r][4]=hi.x; vv[r][5]=hi.y; vv[r][6]=hi.z; vv[r][7]=hi.w;
            }
            #pragma unroll
            for (int kk = 0; kk < 8; ++kk) {
                const float* wr = pW2 + kk * WST;
                ulonglong2 wlo = *(const ulonglong2*)wr;
                ulonglong2 whi = *(const ulonglong2*)(wr + 4);
                #pragma unroll
                for (int r = 0; r < RL; ++r) {
                    u64 vk = dup2(vv[r][kk]);
                    tacc[r][0] = fma2(vk, wlo.x, tacc[r][0]);
                    tacc[r][1] = fma2(vk, wlo.y, tacc[r][1]);
                    tacc[r][2] = fma2(vk, whi.x, tacc[r][2]);
                    tacc[r][3] = fma2(vk, whi.y, tacc[r][3]);
                }
            }
        }
        u64 tf[RL];
        #pragma unroll
        for (int r = 0; r < RL; ++r) {
            u64 keep0 = b0 ? tacc[r][1] : tacc[r][0];
            u64 send0 = b0 ? tacc[r][0] : tacc[r][1];
            u64 keep1 = b0 ? tacc[r][3] : tacc[r][2];
            u64 send1 = b0 ? tacc[r][2] : tacc[r][3];
            u64 a0 = add2(keep0, shfl_xor64(send0, 4));
            u64 a1 = add2(keep1, shfl_xor64(send1, 4));
            u64 mine  = b1s ? a1 : a0;
            u64 sendv = b1s ? a0 : a1;
            tf[r] = add2(mine, shfl_xor64(sendv, 8));
        }
        __syncwarp();   // MV2 act reads done before next iteration's L1 stores

        // ---- epilogue: v1 = sig1 .* t over my 2 rows; 16-thread butterfly ----
        float g0[RL], g1[RL];
        #pragma unroll
        for (int r = 0; r < RL; ++r) {
            u64 v1 = mul2(s1p[r], tf[r]);
            float a, b;
            unpack2(mul2(v1, w1apk), a, b); g0[r] = a + b;
            unpack2(mul2(v1, w1bpk), a, b); g1[r] = a + b;
            u64 G = pack2(g0[r], g1[r]);
            G = add2(G, shfl_xor64(G, 1));
            G = add2(G, shfl_xor64(G, 2));
            G = add2(G, shfl_xor64(G, 4));
            G = add2(G, shfl_xor64(G, 8));
            unpack2(G, g0[r], g1[r]);
        }

        if ((tid & 15) == 0)
            *(float4*)(out + (size_t)t * BB + gbase) =
                make_float4(g0[0], g0[1], g0[2], g0[3]);

        gam[0] = fmaf(hc[0], -g1[0], gam[0]);
        gam[1] = fmaf(hc[1], -g1[1], gam[1]);
        gam[2] = fmaf(hc[2], -g1[2], gam[2]);
        gam[3] = fmaf(hc[3], -g1[3], gam[3]);

        ec[0]=en4.x; ec[1]=en4.y; ec[2]=en4.z; ec[3]=en4.w;
        hc[0]=hn4.x; hc[1]=hn4.y; hc[2]=hn4.z; hc[3]=hn4.w;
    }
}

extern "C" void kernel_launch(void* const* d_in, const int* in_sizes, int n_in,
                              void* d_out, int out_size) {
    const float* eps = (const float*)d_in[0];
    const float* hs  = (const float*)d_in[1];
    const float* W1  = (const float*)d_in[2];
    const float* b1  = (const float*)d_in[3];
    const float* W2  = (const float*)d_in[4];
    const float* b2  = (const float*)d_in[5];
    const float* W3  = (const float*)d_in[6];
    float* out = (float*)d_out;

    // 16384 lanes / 128 per CTA = 128 CTAs x 512 threads
    // -> 65536 threads, 4 warps/SMSP on 128 SMs, split-K over 4 threads
    rnncell_q4_kernel<<<BB / LPC, BLK>>>(eps, hs, W1, b1, W2, b2, W3, out);
}